// round 11
// baseline (speedup 1.0000x reference)
#include <cuda_runtime.h>
#include <math.h>

#define C_IN  64
#define C_HID 64
#define C_OUT 40
#define NMAX  50000
#define EMAX  800000

// Scratch (allocation-free rule). 16B aligned for float4 ops on MY buffers.
__device__ __align__(16) float g_h1[NMAX * C_HID];   // x @ W1 (UNSCALED)
__device__ __align__(16) float g_h2s[NMAX * C_OUT];  // (feat @ W2) * dinv[row]
__device__ int   g_deg[NMAX];
__device__ float g_dinv[NMAX];
__device__ int   g_start[NMAX];   // CSR range base per dst (unordered bases)
__device__ int   g_cursor[NMAX];  // placement cursors
__device__ int   g_csr[EMAX];     // src ids grouped by dst
__device__ int   g_total;         // ticket counter for range allocation

// ---------------------------------------------------------------------------
__global__ void zero_deg_kernel(int N) {
    int i = blockIdx.x * blockDim.x + threadIdx.x;
    if (i < N) g_deg[i] = 0;
    if (i == 0) g_total = 0;
}

__global__ void deg_kernel(const int* __restrict__ ei, int E) {
    int e = blockIdx.x * blockDim.x + threadIdx.x;
    if (e < E) atomicAdd(&g_deg[ei[E + e]], 1);
}

// ---------------------------------------------------------------------------
// Scan-free CSR range allocation: block-local exclusive scan of 512 degrees
// (warp shuffles), ONE atomicAdd per block claims the base. Ranges are
// disjoint/contiguous but NOT id-ordered -> consumers use start + deg.
// Also emits cursor and dinv.  (proven R10)
// ---------------------------------------------------------------------------
__global__ void __launch_bounds__(256)
alloc_kernel(int N) {
    __shared__ int warp_sums[8];
    __shared__ int s_base;
    int t    = threadIdx.x;
    int lane = t & 31;
    int wid  = t >> 5;
    int i0   = blockIdx.x * 512 + 2 * t;

    int a = (i0 < N)     ? g_deg[i0]     : 0;
    int b = (i0 + 1 < N) ? g_deg[i0 + 1] : 0;
    int pair = a + b;

    int v = pair;
#pragma unroll
    for (int o = 1; o < 32; o <<= 1) {
        int u = __shfl_up_sync(0xFFFFFFFFu, v, o);
        if (lane >= o) v += u;
    }
    if (lane == 31) warp_sums[wid] = v;
    __syncthreads();
    if (wid == 0) {
        int w = (lane < 8) ? warp_sums[lane] : 0;
#pragma unroll
        for (int o = 1; o < 32; o <<= 1) {
            int u = __shfl_up_sync(0xFFFFFFFFu, w, o);
            if (lane >= o) w += u;
        }
        if (lane < 8) warp_sums[lane] = w;
    }
    __syncthreads();
    int carry = (wid > 0) ? warp_sums[wid - 1] : 0;
    int incl  = v + carry;                 // inclusive over block (pairs)
    if (t == 255) s_base = atomicAdd(&g_total, incl);
    __syncthreads();
    int excl = incl - pair + s_base;       // this pair's global base
    if (i0 < N) {
        g_start[i0]  = excl;
        g_cursor[i0] = excl;
        g_dinv[i0]   = rsqrtf((float)(a + 1));
    }
    if (i0 + 1 < N) {
        g_start[i0 + 1]  = excl + a;
        g_cursor[i0 + 1] = excl + a;
        g_dinv[i0 + 1]   = rsqrtf((float)(b + 1));
    }
}

__global__ void fill_csr_kernel(const int* __restrict__ ei, int E) {
    int e = blockIdx.x * blockDim.x + threadIdx.x;
    if (e < E) {
        int s = ei[e];
        int d = ei[E + e];
        int p = atomicAdd(&g_cursor[d], 1);
        g_csr[p] = s;
    }
}

// ---------------------------------------------------------------------------
// gemm1: g_h1[r,:] = x[r,:] @ W1 (unscaled). K = COUT = 64.
// 64-row tiles, 256 threads, 2x2 micro-tile per thread:
//   cols {tx, tx+32}, rows {r, r+32} with r = ty..31 step 8.
// Per warp-k: 4 LDS wavefronts -> 4 warp-FMAs (half the LDS/FMA of R7).
// ---------------------------------------------------------------------------
__global__ void __launch_bounds__(256)
gemm1_kernel(const float* __restrict__ X, const float* __restrict__ W, int N) {
    constexpr int C = 64;
    __shared__ float Xs[64 * C];
    __shared__ float Ws[C * C];

    const int tx  = threadIdx.x;   // 0..31
    const int ty  = threadIdx.y;   // 0..7
    const int tid = ty * 32 + tx;
    const int row0 = blockIdx.x * 64;

    for (int i = tid; i < C * C / 4; i += 256)
        ((float4*)Ws)[i] = ((const float4*)W)[i];

    int nrows = min(64, N - row0);
    for (int i = tid; i < nrows * (C / 4); i += 256) {
        ((float4*)Xs)[i] = ((const float4*)(X + (size_t)row0 * C))[i];
    }
    __syncthreads();

    for (int r = ty; r < 32; r += 8) {
        float a00 = 0.f, a01 = 0.f, a10 = 0.f, a11 = 0.f;
#pragma unroll
        for (int k = 0; k < C; k++) {
            float x0 = Xs[r * C + k];
            float x1 = Xs[(r + 32) * C + k];
            float w0 = Ws[k * C + tx];
            float w1 = Ws[k * C + tx + 32];
            a00 = fmaf(x0, w0, a00);
            a01 = fmaf(x0, w1, a01);
            a10 = fmaf(x1, w0, a10);
            a11 = fmaf(x1, w1, a11);
        }
        int r_hi = row0 + r + 32;
        g_h1[(size_t)(row0 + r) * C + tx]      = a00;
        g_h1[(size_t)(row0 + r) * C + tx + 32] = a01;
        if (r_hi < N) {
            g_h1[(size_t)r_hi * C + tx]      = a10;
            g_h1[(size_t)r_hi * C + tx + 32] = a11;
        }
    }
}

// ---------------------------------------------------------------------------
// Fused agg1 + gemm2. One block per 64-node tile. (proven R10)
// Phase 1: half-warp per node (4 nodes each):
//   feat[n] = relu(dinv[n]*(dinv[n]*h1[n] + sum_s dinv[s]*h1[s]) + b1) -> smem
// Phase 2: h2s[r,:] = (feat[r,:] @ W2) * dinv[r] straight from smem.
// ---------------------------------------------------------------------------
__global__ void __launch_bounds__(256)
ag_kernel(const float* __restrict__ b1, const float* __restrict__ W2, int N) {
    __shared__ float Fs[64 * C_HID];
    __shared__ float Ws[C_HID * C_OUT];

    int tid  = threadIdx.x;
    int row0 = blockIdx.x * 64;

    for (int i = tid; i < C_HID * C_OUT; i += 256) Ws[i] = W2[i];

    int hw  = tid >> 4;   // half-warp id 0..15
    int sub = tid & 15;   // float4 chunk 0..15
    const float4* hs = (const float4*)g_h1;

#pragma unroll
    for (int t = 0; t < 4; t++) {
        int nl   = hw * 4 + t;       // 0..63
        int node = row0 + nl;
        if (node < N) {
            float dn = g_dinv[node];
            float4 self = hs[node * 16 + sub];
            float4 acc;
            acc.x = self.x * dn; acc.y = self.y * dn;
            acc.z = self.z * dn; acc.w = self.w * dn;

            int i = g_start[node], end = i + g_deg[node];
#pragma unroll 4
            for (; i < end; i++) {
                int s = g_csr[i];
                float ds = g_dinv[s];
                float4 a = hs[s * 16 + sub];
                acc.x = fmaf(a.x, ds, acc.x);
                acc.y = fmaf(a.y, ds, acc.y);
                acc.z = fmaf(a.z, ds, acc.z);
                acc.w = fmaf(a.w, ds, acc.w);
            }
            int c = sub * 4;
            float4 o;
            o.x = fmaxf(fmaf(acc.x, dn, b1[c + 0]), 0.f);
            o.y = fmaxf(fmaf(acc.y, dn, b1[c + 1]), 0.f);
            o.z = fmaxf(fmaf(acc.z, dn, b1[c + 2]), 0.f);
            o.w = fmaxf(fmaf(acc.w, dn, b1[c + 3]), 0.f);
            *(float4*)(Fs + nl * C_HID + c) = o;
        }
    }
    __syncthreads();

    // GEMM phase: 240 active threads, thread-per-column.
    if (tid < 240) {
        int c  = tid % C_OUT;
        int r0 = tid / C_OUT;  // 0..5
        int nrows = min(64, N - row0);
        for (int r = r0; r < nrows; r += 6) {
            float acc = 0.f;
#pragma unroll
            for (int k = 0; k < C_HID; k++) acc += Fs[r * C_HID + k] * Ws[k * C_OUT + c];
            g_h2s[(size_t)(row0 + r) * C_OUT + c] = acc * g_dinv[row0 + r];
        }
    }
}

// ---------------------------------------------------------------------------
// Layer-2 aggregate + bias + log_softmax (h2s pre-scaled by dinv[src]).
// ---------------------------------------------------------------------------
__global__ void agg2_kernel(const float* __restrict__ b2,
                            float* __restrict__ out, int N) {
    int lane = threadIdx.x & 31;
    int warp = (blockIdx.x * blockDim.x + threadIdx.x) >> 5;
    int node = warp * 2 + (lane >> 4);
    int sub  = lane & 15;
    bool valid = (node < N) && (sub < 10);
    int nc = (node < N) ? node : 0;

    float4 v = make_float4(-INFINITY, -INFINITY, -INFINITY, -INFINITY);
    if (valid) {
        const float4* hs = (const float4*)g_h2s;
        float4 acc = hs[nc * 10 + sub];  // self loop
        int i = g_start[nc], end = i + g_deg[nc];
#pragma unroll 4
        for (; i < end; i++) {
            float4 a = hs[g_csr[i] * 10 + sub];
            acc.x += a.x; acc.y += a.y; acc.z += a.z; acc.w += a.w;
        }
        float di = g_dinv[nc];
        int c = sub * 4;
        v = make_float4(fmaf(acc.x, di, b2[c + 0]),
                        fmaf(acc.y, di, b2[c + 1]),
                        fmaf(acc.z, di, b2[c + 2]),
                        fmaf(acc.w, di, b2[c + 3]));
    }

    float m = fmaxf(fmaxf(v.x, v.y), fmaxf(v.z, v.w));
#pragma unroll
    for (int o = 8; o; o >>= 1) m = fmaxf(m, __shfl_xor_sync(0xFFFFFFFFu, m, o));

    float s = valid ? (expf(v.x - m) + expf(v.y - m) + expf(v.z - m) + expf(v.w - m))
                    : 0.f;
#pragma unroll
    for (int o = 8; o; o >>= 1) s += __shfl_xor_sync(0xFFFFFFFFu, s, o);

    float lg = m + logf(s);
    if (valid) {
        float4 o4 = make_float4(v.x - lg, v.y - lg, v.z - lg, v.w - lg);
        ((float4*)out)[nc * 10 + sub] = o4;
    }
}

// ---------------------------------------------------------------------------
extern "C" void kernel_launch(void* const* d_in, const int* in_sizes, int n_in,
                              void* d_out, int out_size) {
    const float* x  = (const float*)d_in[0];
    const int*   ei = (const int*)d_in[1];
    const float* W1 = (const float*)d_in[2];
    const float* b1 = (const float*)d_in[3];
    const float* W2 = (const float*)d_in[4];
    const float* b2 = (const float*)d_in[5];
    float* out = (float*)d_out;

    int N = in_sizes[0] / C_IN;
    int E = in_sizes[1] / 2;
    int G = (N + 63) / 64;

    zero_deg_kernel<<<(N + 255) / 256, 256>>>(N);
    deg_kernel<<<(E + 255) / 256, 256>>>(ei, E);
    alloc_kernel<<<(N + 511) / 512, 256>>>(N);
    fill_csr_kernel<<<(E + 255) / 256, 256>>>(ei, E);
    gemm1_kernel<<<G, dim3(32, 8)>>>(x, W1, N);
    ag_kernel<<<G, 256>>>(b1, W2, N);
    agg2_kernel<<<(N + 15) / 16, 256>>>(b2, out, N);
}

// round 12
// speedup vs baseline: 1.0453x; 1.0453x over previous
#include <cuda_runtime.h>
#include <math.h>

#define C_IN  64
#define C_HID 64
#define C_OUT 40
#define NMAX  50000
#define EMAX  800000

// Scratch (allocation-free rule). 16B aligned for float4 ops on MY buffers.
__device__ __align__(16) float g_h1[NMAX * C_HID];   // x @ W1 (UNSCALED)
__device__ __align__(16) float g_h2s[NMAX * C_OUT];  // (feat @ W2) * dinv[row]
__device__ int   g_deg[NMAX];     // zeroed by alloc_kernel after use
__device__ float g_dinv[NMAX];
__device__ int   g_start[NMAX];   // CSR range base per dst (unordered bases)
__device__ int   g_cursor[NMAX];  // placement cursor; == range END after fill
__device__ int   g_csr[EMAX];     // src ids grouped by dst
__device__ int   g_total;         // ticket counter; reset by agg2

// ---------------------------------------------------------------------------
// Shared GEMM tile body (R7-proven): thread-per-output-column, 64-row tiles.
// ---------------------------------------------------------------------------
template <int CIN, int COUT>
__device__ __forceinline__ void gemm_tile(const float* __restrict__ Xin,
                                          const float* __restrict__ W,
                                          float* __restrict__ H,
                                          int N, int row0) {
    constexpr int ROWS = 64;
    __shared__ float Ws[CIN * COUT];
    __shared__ float Xs[ROWS * CIN];

    int tid  = threadIdx.y * blockDim.x + threadIdx.x;
    int nthr = blockDim.x * blockDim.y;

    for (int i = tid; i < CIN * COUT; i += nthr) Ws[i] = W[i];

    int nrows = min(ROWS, N - row0);
    for (int i = tid; i < nrows * CIN; i += nthr) Xs[i] = Xin[(size_t)row0 * CIN + i];
    __syncthreads();

    int c = threadIdx.x;
    for (int r = threadIdx.y; r < nrows; r += blockDim.y) {
        float acc = 0.f;
#pragma unroll
        for (int k = 0; k < CIN; k++) acc += Xs[r * CIN + k] * Ws[k * COUT + c];
        H[(size_t)(row0 + r) * COUT + c] = acc;
    }
}

// ---------------------------------------------------------------------------
// Fused A: first half of gemm1 (unscaled) || degree histogram (4 edges/thread
// via int4 loads for MLP; edge kernels are latency-bound per R11 profile).
// ---------------------------------------------------------------------------
__global__ void __launch_bounds__(256)
fusedA_kernel(const float* __restrict__ x, const float* __restrict__ W1,
              const int* __restrict__ ei, int E, int N, int GA, int DB) {
    if ((int)blockIdx.x < GA) {
        gemm_tile<C_IN, C_HID>(x, W1, g_h1, N, blockIdx.x * 64);
    } else {
        int tid = threadIdx.y * blockDim.x + threadIdx.x;
        int bid = (int)blockIdx.x - GA;
        const int4* d4 = (const int4*)(ei + E);
        int nq = E >> 2;
        for (int q = bid * 256 + tid; q < nq; q += DB * 256) {
            int4 d = d4[q];
            atomicAdd(&g_deg[d.x], 1);
            atomicAdd(&g_deg[d.y], 1);
            atomicAdd(&g_deg[d.z], 1);
            atomicAdd(&g_deg[d.w], 1);
        }
        // tail
        for (int e = (nq << 2) + bid * 256 + tid; e < E; e += DB * 256)
            atomicAdd(&g_deg[ei[E + e]], 1);
    }
}

// ---------------------------------------------------------------------------
// Scan-free CSR range allocation (proven R10): block-local shuffle scan of
// 512 degrees; ONE atomicAdd claims the block's base. Emits start/cursor/dinv
// and ZEROES g_deg for the next invocation (deg is not read after this).
// ---------------------------------------------------------------------------
__global__ void __launch_bounds__(256)
alloc_kernel(int N) {
    __shared__ int warp_sums[8];
    __shared__ int s_base;
    int t    = threadIdx.x;
    int lane = t & 31;
    int wid  = t >> 5;
    int i0   = blockIdx.x * 512 + 2 * t;

    int a = (i0 < N)     ? g_deg[i0]     : 0;
    int b = (i0 + 1 < N) ? g_deg[i0 + 1] : 0;
    int pair = a + b;

    int v = pair;
#pragma unroll
    for (int o = 1; o < 32; o <<= 1) {
        int u = __shfl_up_sync(0xFFFFFFFFu, v, o);
        if (lane >= o) v += u;
    }
    if (lane == 31) warp_sums[wid] = v;
    __syncthreads();
    if (wid == 0) {
        int w = (lane < 8) ? warp_sums[lane] : 0;
#pragma unroll
        for (int o = 1; o < 32; o <<= 1) {
            int u = __shfl_up_sync(0xFFFFFFFFu, w, o);
            if (lane >= o) w += u;
        }
        if (lane < 8) warp_sums[lane] = w;
    }
    __syncthreads();
    int carry = (wid > 0) ? warp_sums[wid - 1] : 0;
    int incl  = v + carry;                 // inclusive over block (pairs)
    if (t == 255) s_base = atomicAdd(&g_total, incl);
    __syncthreads();
    int excl = incl - pair + s_base;       // this pair's global base
    if (i0 < N) {
        g_start[i0]  = excl;
        g_cursor[i0] = excl;
        g_dinv[i0]   = rsqrtf((float)(a + 1));
        g_deg[i0]    = 0;                  // reset for next invocation
    }
    if (i0 + 1 < N) {
        g_start[i0 + 1]  = excl + a;
        g_cursor[i0 + 1] = excl + a;
        g_dinv[i0 + 1]   = rsqrtf((float)(b + 1));
        g_deg[i0 + 1]    = 0;
    }
}

// ---------------------------------------------------------------------------
// Fused B: second half of gemm1 (unscaled) || CSR fill (4 edges/thread).
// After this kernel, g_cursor[d] == range end for dst d.
// ---------------------------------------------------------------------------
__global__ void __launch_bounds__(256)
fusedB_kernel(const float* __restrict__ x, const float* __restrict__ W1,
              const int* __restrict__ ei, int E, int N, int GA, int GB, int FB) {
    if ((int)blockIdx.x < GB) {
        gemm_tile<C_IN, C_HID>(x, W1, g_h1, N, (GA + blockIdx.x) * 64);
    } else {
        int tid = threadIdx.y * blockDim.x + threadIdx.x;
        int bid = (int)blockIdx.x - GB;
        const int4* s4 = (const int4*)ei;
        const int4* d4 = (const int4*)(ei + E);
        int nq = E >> 2;
        for (int q = bid * 256 + tid; q < nq; q += FB * 256) {
            int4 s = s4[q];
            int4 d = d4[q];
            g_csr[atomicAdd(&g_cursor[d.x], 1)] = s.x;
            g_csr[atomicAdd(&g_cursor[d.y], 1)] = s.y;
            g_csr[atomicAdd(&g_cursor[d.z], 1)] = s.z;
            g_csr[atomicAdd(&g_cursor[d.w], 1)] = s.w;
        }
        for (int e = (nq << 2) + bid * 256 + tid; e < E; e += FB * 256) {
            int s = ei[e];
            int d = ei[E + e];
            g_csr[atomicAdd(&g_cursor[d], 1)] = s;
        }
    }
}

// ---------------------------------------------------------------------------
// Fused agg1 + gemm2 (proven R10). One block per 64-node tile.
// Range end now comes from g_cursor.
// ---------------------------------------------------------------------------
__global__ void __launch_bounds__(256)
ag_kernel(const float* __restrict__ b1, const float* __restrict__ W2, int N) {
    __shared__ float Fs[64 * C_HID];
    __shared__ float Ws[C_HID * C_OUT];

    int tid  = threadIdx.x;
    int row0 = blockIdx.x * 64;

    for (int i = tid; i < C_HID * C_OUT; i += 256) Ws[i] = W2[i];

    int hw  = tid >> 4;   // half-warp id 0..15
    int sub = tid & 15;   // float4 chunk 0..15
    const float4* hs = (const float4*)g_h1;

#pragma unroll
    for (int t = 0; t < 4; t++) {
        int nl   = hw * 4 + t;       // 0..63
        int node = row0 + nl;
        if (node < N) {
            float dn = g_dinv[node];
            float4 self = hs[node * 16 + sub];
            float4 acc;
            acc.x = self.x * dn; acc.y = self.y * dn;
            acc.z = self.z * dn; acc.w = self.w * dn;

            int i = g_start[node], end = g_cursor[node];
#pragma unroll 4
            for (; i < end; i++) {
                int s = g_csr[i];
                float ds = g_dinv[s];
                float4 a = hs[s * 16 + sub];
                acc.x = fmaf(a.x, ds, acc.x);
                acc.y = fmaf(a.y, ds, acc.y);
                acc.z = fmaf(a.z, ds, acc.z);
                acc.w = fmaf(a.w, ds, acc.w);
            }
            int c = sub * 4;
            float4 o;
            o.x = fmaxf(fmaf(acc.x, dn, b1[c + 0]), 0.f);
            o.y = fmaxf(fmaf(acc.y, dn, b1[c + 1]), 0.f);
            o.z = fmaxf(fmaf(acc.z, dn, b1[c + 2]), 0.f);
            o.w = fmaxf(fmaf(acc.w, dn, b1[c + 3]), 0.f);
            *(float4*)(Fs + nl * C_HID + c) = o;
        }
    }
    __syncthreads();

    // GEMM phase: 240 active threads, thread-per-column.
    if (tid < 240) {
        int c  = tid % C_OUT;
        int r0 = tid / C_OUT;  // 0..5
        int nrows = min(64, N - row0);
        for (int r = r0; r < nrows; r += 6) {
            float acc = 0.f;
#pragma unroll
            for (int k = 0; k < C_HID; k++) acc += Fs[r * C_HID + k] * Ws[k * C_OUT + c];
            g_h2s[(size_t)(row0 + r) * C_OUT + c] = acc * g_dinv[row0 + r];
        }
    }
}

// ---------------------------------------------------------------------------
// Layer-2 aggregate + bias + log_softmax (h2s pre-scaled by dinv[src]).
// Also resets g_total for the next invocation.
// ---------------------------------------------------------------------------
__global__ void agg2_kernel(const float* __restrict__ b2,
                            float* __restrict__ out, int N) {
    if (blockIdx.x == 0 && threadIdx.x == 0) g_total = 0;

    int lane = threadIdx.x & 31;
    int warp = (blockIdx.x * blockDim.x + threadIdx.x) >> 5;
    int node = warp * 2 + (lane >> 4);
    int sub  = lane & 15;
    bool valid = (node < N) && (sub < 10);
    int nc = (node < N) ? node : 0;

    float4 v = make_float4(-INFINITY, -INFINITY, -INFINITY, -INFINITY);
    if (valid) {
        const float4* hs = (const float4*)g_h2s;
        float4 acc = hs[nc * 10 + sub];  // self loop
        int i = g_start[nc], end = g_cursor[nc];
#pragma unroll 4
        for (; i < end; i++) {
            float4 a = hs[g_csr[i] * 10 + sub];
            acc.x += a.x; acc.y += a.y; acc.z += a.z; acc.w += a.w;
        }
        float di = g_dinv[nc];
        int c = sub * 4;
        v = make_float4(fmaf(acc.x, di, b2[c + 0]),
                        fmaf(acc.y, di, b2[c + 1]),
                        fmaf(acc.z, di, b2[c + 2]),
                        fmaf(acc.w, di, b2[c + 3]));
    }

    float m = fmaxf(fmaxf(v.x, v.y), fmaxf(v.z, v.w));
#pragma unroll
    for (int o = 8; o; o >>= 1) m = fmaxf(m, __shfl_xor_sync(0xFFFFFFFFu, m, o));

    float s = valid ? (expf(v.x - m) + expf(v.y - m) + expf(v.z - m) + expf(v.w - m))
                    : 0.f;
#pragma unroll
    for (int o = 8; o; o >>= 1) s += __shfl_xor_sync(0xFFFFFFFFu, s, o);

    float lg = m + logf(s);
    if (valid) {
        float4 o4 = make_float4(v.x - lg, v.y - lg, v.z - lg, v.w - lg);
        ((float4*)out)[nc * 10 + sub] = o4;
    }
}

// ---------------------------------------------------------------------------
extern "C" void kernel_launch(void* const* d_in, const int* in_sizes, int n_in,
                              void* d_out, int out_size) {
    const float* x  = (const float*)d_in[0];
    const int*   ei = (const int*)d_in[1];
    const float* W1 = (const float*)d_in[2];
    const float* b1 = (const float*)d_in[3];
    const float* W2 = (const float*)d_in[4];
    const float* b2 = (const float*)d_in[5];
    float* out = (float*)d_out;

    int N = in_sizes[0] / C_IN;
    int E = in_sizes[1] / 2;

    int G  = (N + 63) / 64;   // gemm1 tiles
    int GA = (G + 1) / 2;
    int GB = G - GA;
    int DB = 512;             // deg partner blocks
    int FB = 512;             // fill partner blocks

    fusedA_kernel<<<GA + DB, dim3(64, 4)>>>(x, W1, ei, E, N, GA, DB);
    alloc_kernel<<<(N + 511) / 512, 256>>>(N);
    fusedB_kernel<<<GB + FB, dim3(64, 4)>>>(x, W1, ei, E, N, GA, GB, FB);
    ag_kernel<<<G, 256>>>(b1, W2, N);
    agg2_kernel<<<(N + 15) / 16, 256>>>(b2, out, N);
}